// round 8
// baseline (speedup 1.0000x reference)
#include <cuda_runtime.h>
#include <cuda_fp16.h>
#include <cstring>
#include <cstdint>

#define N_NODES 5000
#define N_EDGES 30000
#define HID     64
#define ED      16
#define H2      4096
#define NCOLS   262144       // 4096*64 columns of M

#define PASS_NODES 512
#define N_PASSES   10        // ceil(5000/512)

// ---------------- static device scratch (no allocs; keep total < ~1.6 GB) ----
__device__ __align__(16) __half g_M0[(size_t)PASS_NODES * NCOLS];  // 268 MB
__device__ __align__(16) __half g_M1[(size_t)PASS_NODES * NCOLS];  // 268 MB
__device__ __align__(16) __half g_hid[(size_t)N_EDGES * H2];       // 246 MB

__device__ int g_off[N_NODES + 1];
__device__ int g_perm[N_EDGES];

// ---------------- fp16 mma (legacy path; tcgen05 rejected: harness PTX
// targets compute_100 without the 'a' feature set) ----------------
__device__ __forceinline__ void mma_f16_k16(float* c,
                                            uint32_t a0, uint32_t a1,
                                            uint32_t a2, uint32_t a3,
                                            uint32_t b0, uint32_t b1) {
    asm volatile(
        "mma.sync.aligned.m16n8k16.row.col.f32.f16.f16.f32 "
        "{%0,%1,%2,%3},{%4,%5,%6,%7},{%8,%9},{%0,%1,%2,%3};"
        : "+f"(c[0]), "+f"(c[1]), "+f"(c[2]), "+f"(c[3])
        : "r"(a0), "r"(a1), "r"(a2), "r"(a3), "r"(b0), "r"(b1));
}

// ---------------- fused single-block CSR build ----------------
__global__ void __launch_bounds__(1024) k_csr(const int* __restrict__ ei) {
    __shared__ int scnt[N_NODES];
    __shared__ int ts[1024];
    int t = threadIdx.x;

    for (int i = t; i < N_NODES; i += 1024) scnt[i] = 0;
    __syncthreads();
    for (int e = t; e < N_EDGES; e += 1024) atomicAdd(&scnt[ei[e]], 1);
    __syncthreads();

    int c[5];
    int base = t * 5;
    int s = 0;
#pragma unroll
    for (int u = 0; u < 5; u++) {
        int id = base + u;
        c[u] = (id < N_NODES) ? scnt[id] : 0;
        s += c[u];
    }
    ts[t] = s;
    __syncthreads();
    for (int ofs = 1; ofs < 1024; ofs <<= 1) {
        int v = (t >= ofs) ? ts[t - ofs] : 0;
        __syncthreads();
        ts[t] += v;
        __syncthreads();
    }
    int ex = ts[t] - s;
#pragma unroll
    for (int u = 0; u < 5; u++) {
        int id = base + u;
        if (id < N_NODES) { g_off[id] = ex; scnt[id] = ex; }
        ex += c[u];
    }
    if (t == 0) g_off[N_NODES] = N_EDGES;
    __syncthreads();
    for (int e = t; e < N_EDGES; e += 1024) {
        int pos = atomicAdd(&scnt[ei[e]], 1);
        g_perm[pos] = e;
    }
}

// ---------------- hid = relu(edge_attr @ W1 + b1), fp16 output ----------------
#define HID_EB 8
__global__ void k_hid(const float* __restrict__ ea,
                      const float* __restrict__ W1,
                      const float* __restrict__ b1) {
    __shared__ float eaS[HID_EB][ED];
    int e0 = blockIdx.x * HID_EB;
    int tid = threadIdx.x;
    if (tid < HID_EB * ED) {
        int e = tid / ED, t = tid % ED;
        eaS[e][t] = ea[(size_t)(e0 + e) * ED + t];
    }
    __syncthreads();
    for (int k = tid; k < H2; k += 256) {
        float acc[HID_EB];
        float bv = b1[k];
#pragma unroll
        for (int e = 0; e < HID_EB; e++) acc[e] = bv;
#pragma unroll
        for (int t = 0; t < ED; t++) {
            float w = W1[t * H2 + k];
#pragma unroll
            for (int e = 0; e < HID_EB; e++) acc[e] = fmaf(eaS[e][t], w, acc[e]);
        }
#pragma unroll
        for (int e = 0; e < HID_EB; e++)
            g_hid[(size_t)(e0 + e) * H2 + k] = __float2half_rn(fmaxf(acc[e], 0.0f));
    }
}

// ================= fused pass kernel =================
// Grid = [stage_cnt stage2-blocks of pass (p-1)] ++ [8192 gemm-blocks of pass p]
// gemm writes buf p&1; stage2 reads buf (p-1)&1 — independent, overlap freely.
//
// GEMM: M[n,c] = sum_j h[n,j]*W2flat[c*64+j], 2-term split:
//   h = ah+al (fp16 pair, exact to ~2^-22), W2 -> single fp16 (the only
//   quantization, ~1.4e-4 RMS). mma.m16n8k16, tile 128 nodes x 128 cols.
// smem (49152 B): BF[nt16][ks4][lane32] uint2(b0,b1) 16KB |
//                 AH,AL[mt8][ks4][lane32] uint4(a0..a3) 16+16KB
#define OFF_BF 0
#define OFF_AH 16384
#define OFF_AL 32768
#define FUSED_SMEM 49152

extern __shared__ __align__(16) char smdyn[];

__device__ __forceinline__ void gemm_body(const float* __restrict__ h,
                                          const float* __restrict__ W2,
                                          __half* __restrict__ Mw,
                                          int pass, int gb) {
    int tid = threadIdx.x;
    int w = tid >> 5, lane = tid & 31;
    int colb = gb & 2047, rowg = gb >> 11;
    int n0 = pass * PASS_NODES + rowg * 128;
    int rowloc0 = rowg * 128;
    size_t c0 = (size_t)colb * 128;

    // ---- fill B fragments: 128 cols x 64 j, single fp16 ----
    for (int idx = tid; idx < 128 * 64; idx += 256) {
        int c = idx >> 6, j = idx & 63;
        float v = W2[(c0 + c) * 64 + j];
        __half hb = __float2half_rn(v);
        int nt = c >> 3, colin = c & 7;
        int ks = j >> 4, kk = j & 15;
        int flane = colin * 4 + ((kk & 7) >> 1);
        int reg = kk >> 3;
        int half_sel = kk & 1;
        uint32_t off = (uint32_t)(((nt * 4 + ks) * 32 + flane) * 8 + reg * 4 +
                                  half_sel * 2);
        *(__half*)(smdyn + OFF_BF + off) = hb;
    }
    // ---- fill A fragments (hi/lo split): 128 nodes x 64 j ----
    for (int idx = tid; idx < 128 * 64; idx += 256) {
        int m = idx >> 6, j = idx & 63;
        int n = n0 + m;
        float v = (n < N_NODES) ? h[(size_t)n * 64 + j] : 0.0f;
        __half hi = __float2half_rn(v);
        __half lo = __float2half_rn(v - __half2float(hi));
        int mt = m >> 4, mm = m & 15;
        int ks = j >> 4, kk = j & 15;
        int flane = (mm & 7) * 4 + ((kk & 7) >> 1);
        int reg = (mm >> 3) | ((kk >> 3) << 1);
        int half_sel = kk & 1;
        uint32_t off = (uint32_t)(((mt * 4 + ks) * 32 + flane) * 16 + reg * 4 +
                                  half_sel * 2);
        *(__half*)(smdyn + OFF_AH + off) = hi;
        *(__half*)(smdyn + OFF_AL + off) = lo;
    }
    __syncthreads();

    float acc[16][4];
#pragma unroll
    for (int nt = 0; nt < 16; nt++)
#pragma unroll
        for (int r = 0; r < 4; r++) acc[nt][r] = 0.0f;

#pragma unroll
    for (int ks = 0; ks < 4; ks++) {
        uint4 ah = *(const uint4*)(smdyn + OFF_AH + ((w * 4 + ks) * 32 + lane) * 16);
        uint4 al = *(const uint4*)(smdyn + OFF_AL + ((w * 4 + ks) * 32 + lane) * 16);
#pragma unroll
        for (int nt = 0; nt < 16; nt++) {
            uint2 b = *(const uint2*)(smdyn + OFF_BF + ((nt * 4 + ks) * 32 + lane) * 8);
            mma_f16_k16(acc[nt], ah.x, ah.y, ah.z, ah.w, b.x, b.y);   // Ah*B
            mma_f16_k16(acc[nt], al.x, al.y, al.z, al.w, b.x, b.y);   // Al*B
        }
    }

    // ---- epilogue: fp16 convert, smem restage (pitch 272B), STG.128 ----
    __syncthreads();                    // all warps done reading fragments
    uint32_t wbase = (uint32_t)w * 4352;   // 16 rows * 272 B per warp
    int r = lane >> 2, cq = lane & 3;
#pragma unroll
    for (int nt = 0; nt < 16; nt++) {
        *(__half2*)(smdyn + wbase + r * 272 + nt * 16 + cq * 4) =
            __floats2half2_rn(acc[nt][0], acc[nt][1]);
        *(__half2*)(smdyn + wbase + (r + 8) * 272 + nt * 16 + cq * 4) =
            __floats2half2_rn(acc[nt][2], acc[nt][3]);
    }
    __syncwarp();
    int rr = lane >> 3, seg = lane & 7;
#pragma unroll
    for (int it = 0; it < 4; it++) {
#pragma unroll
        for (int j = 0; j < 2; j++) {
            int r2 = rr + it * 4;
            uint4 vv = *(const uint4*)(smdyn + wbase + r2 * 272 + (seg * 2 + j) * 16);
            int gr = rowloc0 + w * 16 + r2;          // local row in pass buffer
            size_t col = c0 + (size_t)(seg * 2 + j) * 8;
            __stcs((uint4*)(Mw + (size_t)gr * NCOLS + col), vv);
        }
    }
}

// Stage2: m[e,i] = sum_k hid[e,k]*M[n,k*64+i] + (h[n]·b2 view)[i]
#define S2_BODY(NACC)                                                         \
    _Pragma("unroll 4")                                                       \
    for (int k = 0; k < 128; k++) {                                           \
        float2 mm = *(const float2*)&Ms[k * 64 + i2];                         \
        float h0 = hidS[s * 128 + k];                                         \
        a0.x = fmaf(h0, mm.x, a0.x);                                          \
        a0.y = fmaf(h0, mm.y, a0.y);                                          \
        if (NACC > 1) {                                                       \
            float h1 = hidS[(s + 8) * 128 + k];                               \
            a1.x = fmaf(h1, mm.x, a1.x);                                      \
            a1.y = fmaf(h1, mm.y, a1.y);                                      \
        }                                                                     \
        if (NACC > 2) {                                                       \
            float h2v = hidS[(s + 16) * 128 + k];                             \
            a2.x = fmaf(h2v, mm.x, a2.x);                                     \
            a2.y = fmaf(h2v, mm.y, a2.y);                                     \
        }                                                                     \
    }

__device__ __forceinline__ void stage2_body(const float* __restrict__ h,
                                            const float* __restrict__ b2,
                                            const __half* __restrict__ Mr,
                                            float* __restrict__ out,
                                            int pass) {
    float* Ms = (float*)smdyn;                    // 32 KB [k128][i64]
    float* hidS = (float*)(smdyn + 32768);        // 12 KB [slot24][k128]
    float* hS = (float*)(smdyn + 45056);          // 64
    float* cb = (float*)(smdyn + 45312);          // 64
    int* eS = (int*)(smdyn + 45568);              // 24

    int n = pass * PASS_NODES + blockIdx.x;
    if (n >= N_NODES) return;
    int start = g_off[n], end = g_off[n + 1];
    if (start == end) return;

    int tid = threadIdx.x;
    int s = tid >> 5;
    int il = tid & 31;
    int i2 = il * 2;

    if (tid < 64) hS[tid] = h[(size_t)n * 64 + tid];
    __syncthreads();
    if (s == 0) {
        float c0 = 0.f, c1 = 0.f;
#pragma unroll 8
        for (int j = 0; j < 64; j++) {
            float hv = hS[j];
            c0 = fmaf(b2[i2 * 64 + j], hv, c0);
            c1 = fmaf(b2[(i2 + 1) * 64 + j], hv, c1);
        }
        cb[i2] = c0; cb[i2 + 1] = c1;
    }

    const __half* Mrow = Mr + (size_t)(n - pass * PASS_NODES) * NCOLS;

    for (int base = start; base < end; base += 24) {
        int cnt = min(24, end - base);
        __syncthreads();
        if (tid < cnt) eS[tid] = g_perm[base + tid];
        __syncthreads();

        float2 a0 = make_float2(cb[i2], cb[i2 + 1]);
        float2 a1 = a0, a2 = a0;
        int nacc = (s < cnt) + (s + 8 < cnt) + (s + 16 < cnt);

        for (int kc = 0; kc < 32; kc++) {
            __syncthreads();
            const uint4* msrc = (const uint4*)(Mrow + (size_t)kc * 8192);
            for (int u = tid; u < 1024; u += 256) {
                uint4 raw = __ldcs(msrc + u);
                __half2* hp = (__half2*)&raw;
                float2 f0 = __half22float2(hp[0]);
                float2 f1 = __half22float2(hp[1]);
                float2 f2 = __half22float2(hp[2]);
                float2 f3 = __half22float2(hp[3]);
                ((float4*)Ms)[2 * u]     = make_float4(f0.x, f0.y, f1.x, f1.y);
                ((float4*)Ms)[2 * u + 1] = make_float4(f2.x, f2.y, f3.x, f3.y);
            }
            for (int u = tid; u < cnt * 32; u += 256) {
                int v = u >> 5, q = u & 31;
                const uint2* hsrc =
                    (const uint2*)(g_hid + (size_t)eS[v] * H2 + kc * 128);
                uint2 raw = __ldcs(hsrc + q);
                __half2* hp = (__half2*)&raw;
                float2 f0 = __half22float2(hp[0]);
                float2 f1 = __half22float2(hp[1]);
                ((float4*)(hidS + v * 128))[q] = make_float4(f0.x, f0.y, f1.x, f1.y);
            }
            __syncthreads();
            switch (nacc) {
                case 1: { S2_BODY(1) } break;
                case 2: { S2_BODY(2) } break;
                case 3: { S2_BODY(3) } break;
                default: break;
            }
        }
        if (nacc > 0) *(float2*)&out[(size_t)eS[s] * 64 + i2] = a0;
        if (nacc > 1) *(float2*)&out[(size_t)eS[s + 8] * 64 + i2] = a1;
        if (nacc > 2) *(float2*)&out[(size_t)eS[s + 16] * 64 + i2] = a2;
    }
}

__global__ void __launch_bounds__(256, 2) k_fused(const float* __restrict__ h,
                                                  const float* __restrict__ W2,
                                                  const float* __restrict__ b2,
                                                  float* __restrict__ out,
                                                  int gemm_pass, int stage_pass,
                                                  int stage_cnt) {
    if ((int)blockIdx.x < stage_cnt) {
        const __half* Mr = (stage_pass & 1) ? g_M1 : g_M0;
        stage2_body(h, b2, Mr, out, stage_pass);
        return;
    }
    __half* Mw = (gemm_pass & 1) ? g_M1 : g_M0;
    gemm_body(h, W2, Mw, gemm_pass, (int)blockIdx.x - stage_cnt);
}

// ---------------- dst passthrough ----------------
__global__ void k_dst(const int* __restrict__ ei, float* __restrict__ out) {
    int e = blockIdx.x * blockDim.x + threadIdx.x;
    if (e < N_EDGES) out[(size_t)N_EDGES * 64 + e] = (float)ei[N_EDGES + e];
}

// ---------------- launch ----------------
extern "C" void kernel_launch(void* const* d_in, const int* in_sizes, int n_in,
                              void* d_out, int out_size) {
    const float* h  = (const float*)d_in[0];
    const int*   ei = (const int*)d_in[1];
    const float* ea = (const float*)d_in[2];
    const float* W1 = (const float*)d_in[3];
    const float* b1 = (const float*)d_in[4];
    const float* W2 = (const float*)d_in[5];
    const float* b2 = (const float*)d_in[6];
    float* out = (float*)d_out;

    k_csr<<<1, 1024>>>(ei);
    k_hid<<<N_EDGES / HID_EB, 256>>>(ea, W1, b1);

    cudaFuncSetAttribute(k_fused, cudaFuncAttributeMaxDynamicSharedMemorySize,
                         FUSED_SMEM);

    // Software-pipelined passes: launch L runs gemm(pass L) alongside
    // stage2(pass L-1) in one grid; double-buffered M removes dependencies.
    for (int L = 0; L <= N_PASSES; L++) {
        int gp = (L < N_PASSES) ? L : -1;
        int sp = L - 1;
        int scnt = (sp >= 0) ? PASS_NODES : 0;
        int gcnt = (gp >= 0) ? 8192 : 0;      // 2048 col-blocks x 4 row-groups
        k_fused<<<scnt + gcnt, 256, FUSED_SMEM>>>(h, W2, b2, out, gp, sp, scnt);
    }

    if (out_size > N_EDGES * 64)
        k_dst<<<(N_EDGES + 255) / 256, 256>>>(ei, out);
}

// round 10
// speedup vs baseline: 1.0244x; 1.0244x over previous
#include <cuda_runtime.h>
#include <cuda_fp16.h>
#include <cstring>
#include <cstdint>

#define N_NODES 5000
#define N_EDGES 30000
#define HID     64
#define ED      16
#define H2      4096
#define NCOLS   262144       // 4096*64 columns of M

#define PASS_NODES 2048
#define N_PASSES   3         // ceil(5000/2048)

// ---------------- static device scratch (no allocs; keep total < ~1.6 GB) ----
__device__ __align__(16) __half g_M[(size_t)PASS_NODES * NCOLS];   // 1.07 GB
__device__ __align__(16) __half g_hid[(size_t)N_EDGES * H2];       // 246 MB

__device__ int g_off[N_NODES + 1];
__device__ int g_perm[N_EDGES];

// ---------------- fp16 mma (legacy path; tcgen05 rejected: harness PTX
// targets compute_100 without the 'a' feature set) ----------------
__device__ __forceinline__ void mma_f16_k16(float* c,
                                            uint32_t a0, uint32_t a1,
                                            uint32_t a2, uint32_t a3,
                                            uint32_t b0, uint32_t b1) {
    asm volatile(
        "mma.sync.aligned.m16n8k16.row.col.f32.f16.f16.f32 "
        "{%0,%1,%2,%3},{%4,%5,%6,%7},{%8,%9},{%0,%1,%2,%3};"
        : "+f"(c[0]), "+f"(c[1]), "+f"(c[2]), "+f"(c[3])
        : "r"(a0), "r"(a1), "r"(a2), "r"(a3), "r"(b0), "r"(b1));
}

// ---------------- fused single-block CSR build ----------------
__global__ void __launch_bounds__(1024) k_csr(const int* __restrict__ ei) {
    __shared__ int scnt[N_NODES];
    __shared__ int ts[1024];
    int t = threadIdx.x;

    for (int i = t; i < N_NODES; i += 1024) scnt[i] = 0;
    __syncthreads();
    for (int e = t; e < N_EDGES; e += 1024) atomicAdd(&scnt[ei[e]], 1);
    __syncthreads();

    int c[5];
    int base = t * 5;
    int s = 0;
#pragma unroll
    for (int u = 0; u < 5; u++) {
        int id = base + u;
        c[u] = (id < N_NODES) ? scnt[id] : 0;
        s += c[u];
    }
    ts[t] = s;
    __syncthreads();
    for (int ofs = 1; ofs < 1024; ofs <<= 1) {
        int v = (t >= ofs) ? ts[t - ofs] : 0;
        __syncthreads();
        ts[t] += v;
        __syncthreads();
    }
    int ex = ts[t] - s;
#pragma unroll
    for (int u = 0; u < 5; u++) {
        int id = base + u;
        if (id < N_NODES) { g_off[id] = ex; scnt[id] = ex; }
        ex += c[u];
    }
    if (t == 0) g_off[N_NODES] = N_EDGES;
    __syncthreads();
    for (int e = t; e < N_EDGES; e += 1024) {
        int pos = atomicAdd(&scnt[ei[e]], 1);
        g_perm[pos] = e;
    }
}

// ---------------- hid = relu(edge_attr @ W1 + b1), fp16 output ----------------
#define HID_EB 8
__global__ void k_hid(const float* __restrict__ ea,
                      const float* __restrict__ W1,
                      const float* __restrict__ b1) {
    __shared__ float eaS[HID_EB][ED];
    int e0 = blockIdx.x * HID_EB;
    int tid = threadIdx.x;
    if (tid < HID_EB * ED) {
        int e = tid / ED, t = tid % ED;
        eaS[e][t] = ea[(size_t)(e0 + e) * ED + t];
    }
    __syncthreads();
    for (int k = tid; k < H2; k += 256) {
        float acc[HID_EB];
        float bv = b1[k];
#pragma unroll
        for (int e = 0; e < HID_EB; e++) acc[e] = bv;
#pragma unroll
        for (int t = 0; t < ED; t++) {
            float w = W1[t * H2 + k];
#pragma unroll
            for (int e = 0; e < HID_EB; e++) acc[e] = fmaf(eaS[e][t], w, acc[e]);
        }
#pragma unroll
        for (int e = 0; e < HID_EB; e++)
            g_hid[(size_t)(e0 + e) * H2 + k] = __float2half_rn(fmaxf(acc[e], 0.0f));
    }
}

// ---------------- GEMM1 (2-term fp16 split, mma.m16n8k16) ----------------
// M[n,c] = sum_j h[n,j]*W2flat[c*64+j]
//   h = ah+al (fp16 pair, exact to ~2^-22); W2 -> single fp16 (the only
//   quantization here, ~1.4e-4 RMS).  Tile 128 nodes x 128 cols, K=64.
// 256 threads = 8 warps; warp w owns m-tile w (16 rows) x all 16 n-tiles.
// Fragment-ordered smem: one LDS per lane = one full mma fragment.
//   BF[nt16][ks4][lane32] uint2(b0,b1) 16 KB | AH,AL[mt8][ks4][lane32] uint4 16+16 KB
#define OFF_BF 0
#define OFF_AH 16384
#define OFF_AL 32768
#define G1_SMEM 49152

__global__ void __launch_bounds__(256, 2) k_gemm1(const float* __restrict__ h,
                                                  const float* __restrict__ W2,
                                                  int n_base) {
    extern __shared__ __align__(16) char smdyn[];
    int tid = threadIdx.x;
    int w = tid >> 5, lane = tid & 31;
    int n0 = n_base + blockIdx.y * 128;
    int rowloc0 = blockIdx.y * 128;
    size_t c0 = (size_t)blockIdx.x * 128;

    // ---- fill B fragments: 128 cols x 64 j, single fp16 ----
    for (int idx = tid; idx < 128 * 64; idx += 256) {
        int c = idx >> 6, j = idx & 63;
        float v = W2[(c0 + c) * 64 + j];
        __half hb = __float2half_rn(v);
        int nt = c >> 3, colin = c & 7;
        int ks = j >> 4, kk = j & 15;
        int flane = colin * 4 + ((kk & 7) >> 1);
        int reg = kk >> 3;
        int half_sel = kk & 1;
        uint32_t off = (uint32_t)(((nt * 4 + ks) * 32 + flane) * 8 + reg * 4 +
                                  half_sel * 2);
        *(__half*)(smdyn + OFF_BF + off) = hb;
    }
    // ---- fill A fragments (hi/lo split): 128 nodes x 64 j ----
    for (int idx = tid; idx < 128 * 64; idx += 256) {
        int m = idx >> 6, j = idx & 63;
        int n = n0 + m;
        float v = (n < N_NODES) ? h[(size_t)n * 64 + j] : 0.0f;
        __half hi = __float2half_rn(v);
        __half lo = __float2half_rn(v - __half2float(hi));
        int mt = m >> 4, mm = m & 15;
        int ks = j >> 4, kk = j & 15;
        int flane = (mm & 7) * 4 + ((kk & 7) >> 1);
        int reg = (mm >> 3) | ((kk >> 3) << 1);
        int half_sel = kk & 1;
        uint32_t off = (uint32_t)(((mt * 4 + ks) * 32 + flane) * 16 + reg * 4 +
                                  half_sel * 2);
        *(__half*)(smdyn + OFF_AH + off) = hi;
        *(__half*)(smdyn + OFF_AL + off) = lo;
    }
    __syncthreads();

    float acc[16][4];
#pragma unroll
    for (int nt = 0; nt < 16; nt++)
#pragma unroll
        for (int r = 0; r < 4; r++) acc[nt][r] = 0.0f;

#pragma unroll
    for (int ks = 0; ks < 4; ks++) {
        uint4 ah = *(const uint4*)(smdyn + OFF_AH + ((w * 4 + ks) * 32 + lane) * 16);
        uint4 al = *(const uint4*)(smdyn + OFF_AL + ((w * 4 + ks) * 32 + lane) * 16);
#pragma unroll
        for (int nt = 0; nt < 16; nt++) {
            uint2 b = *(const uint2*)(smdyn + OFF_BF + ((nt * 4 + ks) * 32 + lane) * 8);
            mma_f16_k16(acc[nt], ah.x, ah.y, ah.z, ah.w, b.x, b.y);   // Ah*B
            mma_f16_k16(acc[nt], al.x, al.y, al.z, al.w, b.x, b.y);   // Al*B
        }
    }

    // ---- epilogue: fp16 convert, smem restage (pitch 272B), STG.128 ----
    __syncthreads();                       // all warps done reading fragments
    uint32_t wbase = (uint32_t)w * 4352;   // 16 rows * 272 B per warp
    int r = lane >> 2, cq = lane & 3;
#pragma unroll
    for (int nt = 0; nt < 16; nt++) {
        *(__half2*)(smdyn + wbase + r * 272 + nt * 16 + cq * 4) =
            __floats2half2_rn(acc[nt][0], acc[nt][1]);
        *(__half2*)(smdyn + wbase + (r + 8) * 272 + nt * 16 + cq * 4) =
            __floats2half2_rn(acc[nt][2], acc[nt][3]);
    }
    __syncwarp();
    int rr = lane >> 3, seg = lane & 7;
#pragma unroll
    for (int it = 0; it < 4; it++) {
#pragma unroll
        for (int j = 0; j < 2; j++) {
            int r2 = rr + it * 4;
            uint4 vv = *(const uint4*)(smdyn + wbase + r2 * 272 + (seg * 2 + j) * 16);
            int gr = rowloc0 + w * 16 + r2;       // local row in pass buffer
            size_t col = c0 + (size_t)(seg * 2 + j) * 8;
            __stcs((uint4*)(g_M + (size_t)gr * NCOLS + col), vv);
        }
    }
}

// ---------------- Stage 2: m[e,i] = sum_k hid[e,k]*M[n,k*64+i] + cb[i] ----------------
#define S2_BODY(NACC)                                                         \
    _Pragma("unroll 4")                                                       \
    for (int k = 0; k < 128; k++) {                                           \
        float2 mm = *(const float2*)&Ms[k * 64 + i2];                         \
        float h0 = hidS[s * 128 + k];                                         \
        a0.x = fmaf(h0, mm.x, a0.x);                                          \
        a0.y = fmaf(h0, mm.y, a0.y);                                          \
        if (NACC > 1) {                                                       \
            float h1 = hidS[(s + 8) * 128 + k];                               \
            a1.x = fmaf(h1, mm.x, a1.x);                                      \
            a1.y = fmaf(h1, mm.y, a1.y);                                      \
        }                                                                     \
        if (NACC > 2) {                                                       \
            float h2v = hidS[(s + 16) * 128 + k];                             \
            a2.x = fmaf(h2v, mm.x, a2.x);                                     \
            a2.y = fmaf(h2v, mm.y, a2.y);                                     \
        }                                                                     \
    }

__global__ void __launch_bounds__(256) k_stage2(const float* __restrict__ h,
                                                const float* __restrict__ b2,
                                                float* __restrict__ out,
                                                int n_base) {
    __shared__ __align__(16) float Ms[128 * 64];      // 32 KB [k128][i64]
    __shared__ __align__(16) float hidS[24 * 128];    // 12 KB [slot24][k128]
    __shared__ float hS[64];
    __shared__ float cb[64];
    __shared__ int eS[24];

    int n = n_base + blockIdx.x;
    if (n >= N_NODES) return;
    int start = g_off[n], end = g_off[n + 1];
    if (start == end) return;

    int tid = threadIdx.x;
    int s = tid >> 5;
    int il = tid & 31;
    int i2 = il * 2;

    if (tid < 64) hS[tid] = h[(size_t)n * 64 + tid];
    __syncthreads();
    if (s == 0) {
        float c0 = 0.f, c1 = 0.f;
#pragma unroll 8
        for (int j = 0; j < 64; j++) {
            float hv = hS[j];
            c0 = fmaf(b2[i2 * 64 + j], hv, c0);
            c1 = fmaf(b2[(i2 + 1) * 64 + j], hv, c1);
        }
        cb[i2] = c0; cb[i2 + 1] = c1;
    }

    const __half* Mrow = g_M + (size_t)(n - n_base) * NCOLS;

    for (int base = start; base < end; base += 24) {
        int cnt = min(24, end - base);
        __syncthreads();
        if (tid < cnt) eS[tid] = g_perm[base + tid];
        __syncthreads();

        float2 a0 = make_float2(cb[i2], cb[i2 + 1]);
        float2 a1 = a0, a2 = a0;
        int nacc = (s < cnt) + (s + 8 < cnt) + (s + 16 < cnt);

        for (int kc = 0; kc < 32; kc++) {
            __syncthreads();
            const uint4* msrc = (const uint4*)(Mrow + (size_t)kc * 8192);
            for (int u = tid; u < 1024; u += 256) {
                uint4 raw = __ldcs(msrc + u);
                __half2* hp = (__half2*)&raw;
                float2 f0 = __half22float2(hp[0]);
                float2 f1 = __half22float2(hp[1]);
                float2 f2 = __half22float2(hp[2]);
                float2 f3 = __half22float2(hp[3]);
                ((float4*)Ms)[2 * u]     = make_float4(f0.x, f0.y, f1.x, f1.y);
                ((float4*)Ms)[2 * u + 1] = make_float4(f2.x, f2.y, f3.x, f3.y);
            }
            for (int u = tid; u < cnt * 32; u += 256) {
                int v = u >> 5, q = u & 31;
                const uint2* hsrc =
                    (const uint2*)(g_hid + (size_t)eS[v] * H2 + kc * 128);
                uint2 raw = __ldcs(hsrc + q);
                __half2* hp = (__half2*)&raw;
                float2 f0 = __half22float2(hp[0]);
                float2 f1 = __half22float2(hp[1]);
                ((float4*)(hidS + v * 128))[q] = make_float4(f0.x, f0.y, f1.x, f1.y);
            }
            __syncthreads();
            switch (nacc) {
                case 1: { S2_BODY(1) } break;
                case 2: { S2_BODY(2) } break;
                case 3: { S2_BODY(3) } break;
                default: break;
            }
        }
        if (nacc > 0) *(float2*)&out[(size_t)eS[s] * 64 + i2] = a0;
        if (nacc > 1) *(float2*)&out[(size_t)eS[s + 8] * 64 + i2] = a1;
        if (nacc > 2) *(float2*)&out[(size_t)eS[s + 16] * 64 + i2] = a2;
    }
}

// ---------------- dst passthrough ----------------
__global__ void k_dst(const int* __restrict__ ei, float* __restrict__ out) {
    int e = blockIdx.x * blockDim.x + threadIdx.x;
    if (e < N_EDGES) out[(size_t)N_EDGES * 64 + e] = (float)ei[N_EDGES + e];
}

// ---------------- launch ----------------
extern "C" void kernel_launch(void* const* d_in, const int* in_sizes, int n_in,
                              void* d_out, int out_size) {
    const float* h  = (const float*)d_in[0];
    const int*   ei = (const int*)d_in[1];
    const float* ea = (const float*)d_in[2];
    const float* W1 = (const float*)d_in[3];
    const float* b1 = (const float*)d_in[4];
    const float* W2 = (const float*)d_in[5];
    const float* b2 = (const float*)d_in[6];
    float* out = (float*)d_out;

    k_csr<<<1, 1024>>>(ei);
    k_hid<<<N_EDGES / HID_EB, 256>>>(ea, W1, b1);

    cudaFuncSetAttribute(k_gemm1, cudaFuncAttributeMaxDynamicSharedMemorySize,
                         G1_SMEM);

    for (int p = 0; p < N_PASSES; p++) {
        int n_base = p * PASS_NODES;
        dim3 g1(2048, PASS_NODES / 128);     // col-blocks x row-groups
        k_gemm1<<<g1, 256, G1_SMEM>>>(h, W2, n_base);
        k_stage2<<<PASS_NODES, 256>>>(h, b2, out, n_base);
    }

    if (out_size > N_EDGES * 64)
        k_dst<<<(N_EDGES + 255) / 256, 256>>>(ei, out);
}

// round 12
// speedup vs baseline: 1.4068x; 1.3733x over previous
#include <cuda_runtime.h>
#include <cuda_fp16.h>
#include <cstring>
#include <cstdint>

#define N_NODES 5000
#define N_EDGES 30000
#define HID     64
#define ED      16
#define H2      4096
#define NCOLS   262144       // 4096*64 columns of M

#define PASS_NODES 2048
#define N_PASSES   3         // ceil(5000/2048)

// ---------------- static device scratch (no allocs; keep total < ~1.6 GB) ----
__device__ __align__(16) __half g_M[(size_t)PASS_NODES * NCOLS];   // 1.07 GB
__device__ __align__(16) __half g_hid[(size_t)N_EDGES * H2];       // 246 MB

__device__ int g_off[N_NODES + 1];
__device__ int g_perm[N_EDGES];

// ---------------- fp16 mma (legacy path; tcgen05 rejected: harness PTX
// targets compute_100 without the 'a' feature set) ----------------
__device__ __forceinline__ void mma_f16_k16(float* c,
                                            uint32_t a0, uint32_t a1,
                                            uint32_t a2, uint32_t a3,
                                            uint32_t b0, uint32_t b1) {
    asm volatile(
        "mma.sync.aligned.m16n8k16.row.col.f32.f16.f16.f32 "
        "{%0,%1,%2,%3},{%4,%5,%6,%7},{%8,%9},{%0,%1,%2,%3};"
        : "+f"(c[0]), "+f"(c[1]), "+f"(c[2]), "+f"(c[3])
        : "r"(a0), "r"(a1), "r"(a2), "r"(a3), "r"(b0), "r"(b1));
}

// ---------------- fused single-block CSR build ----------------
__global__ void __launch_bounds__(1024) k_csr(const int* __restrict__ ei) {
    __shared__ int scnt[N_NODES];
    __shared__ int ts[1024];
    int t = threadIdx.x;

    for (int i = t; i < N_NODES; i += 1024) scnt[i] = 0;
    __syncthreads();
    for (int e = t; e < N_EDGES; e += 1024) atomicAdd(&scnt[ei[e]], 1);
    __syncthreads();

    int c[5];
    int base = t * 5;
    int s = 0;
#pragma unroll
    for (int u = 0; u < 5; u++) {
        int id = base + u;
        c[u] = (id < N_NODES) ? scnt[id] : 0;
        s += c[u];
    }
    ts[t] = s;
    __syncthreads();
    for (int ofs = 1; ofs < 1024; ofs <<= 1) {
        int v = (t >= ofs) ? ts[t - ofs] : 0;
        __syncthreads();
        ts[t] += v;
        __syncthreads();
    }
    int ex = ts[t] - s;
#pragma unroll
    for (int u = 0; u < 5; u++) {
        int id = base + u;
        if (id < N_NODES) { g_off[id] = ex; scnt[id] = ex; }
        ex += c[u];
    }
    if (t == 0) g_off[N_NODES] = N_EDGES;
    __syncthreads();
    for (int e = t; e < N_EDGES; e += 1024) {
        int pos = atomicAdd(&scnt[ei[e]], 1);
        g_perm[pos] = e;
    }
}

// ---------------- hid = relu(edge_attr @ W1 + b1), fp16 output ----------------
#define HID_EB 8
__global__ void k_hid(const float* __restrict__ ea,
                      const float* __restrict__ W1,
                      const float* __restrict__ b1) {
    __shared__ float eaS[HID_EB][ED];
    int e0 = blockIdx.x * HID_EB;
    int tid = threadIdx.x;
    if (tid < HID_EB * ED) {
        int e = tid / ED, t = tid % ED;
        eaS[e][t] = ea[(size_t)(e0 + e) * ED + t];
    }
    __syncthreads();
    for (int k = tid; k < H2; k += 256) {
        float acc[HID_EB];
        float bv = b1[k];
#pragma unroll
        for (int e = 0; e < HID_EB; e++) acc[e] = bv;
#pragma unroll
        for (int t = 0; t < ED; t++) {
            float w = W1[t * H2 + k];
#pragma unroll
            for (int e = 0; e < HID_EB; e++) acc[e] = fmaf(eaS[e][t], w, acc[e]);
        }
#pragma unroll
        for (int e = 0; e < HID_EB; e++)
            g_hid[(size_t)(e0 + e) * H2 + k] = __float2half_rn(fmaxf(acc[e], 0.0f));
    }
}

// ---------------- GEMM1 (1-term fp16, mma.m16n8k16) ----------------
// M[n,c] = sum_j h[n,j]*W2flat[c*64+j], both operands fp16 (quantization
// ~1.4e-4 RMS each; fp32 accumulate). Tile 128 nodes x 128 cols, K=64.
// Legacy HMMA ceiling ~130-160 TF/s is the bound -> minimize FLOPs.
// Fragment-ordered smem: one LDS per lane = one full mma fragment.
//   BF[nt16][ks4][lane32] uint2(b0,b1) 16 KB | AH[mt8][ks4][lane32] uint4 16 KB
// Epilogue restage needs 8 warps * 4352 B = 34816 B (> the 32 KB fragment
// area!) -> smem size is the MAX of the two phases, 34816.
#define OFF_BF 0
#define OFF_AH 16384
#define G1_SMEM 34816

__global__ void __launch_bounds__(256, 2) k_gemm1(const float* __restrict__ h,
                                                  const float* __restrict__ W2,
                                                  int n_base) {
    extern __shared__ __align__(16) char smdyn[];
    int tid = threadIdx.x;
    int w = tid >> 5, lane = tid & 31;
    int n0 = n_base + blockIdx.y * 128;
    int rowloc0 = blockIdx.y * 128;
    size_t c0 = (size_t)blockIdx.x * 128;

    // ---- fill B fragments: 128 cols x 64 j ----
    for (int idx = tid; idx < 128 * 64; idx += 256) {
        int c = idx >> 6, j = idx & 63;
        float v = W2[(c0 + c) * 64 + j];
        __half hb = __float2half_rn(v);
        int nt = c >> 3, colin = c & 7;
        int ks = j >> 4, kk = j & 15;
        int flane = colin * 4 + ((kk & 7) >> 1);
        int reg = kk >> 3;
        int half_sel = kk & 1;
        uint32_t off = (uint32_t)(((nt * 4 + ks) * 32 + flane) * 8 + reg * 4 +
                                  half_sel * 2);
        *(__half*)(smdyn + OFF_BF + off) = hb;
    }
    // ---- fill A fragments: 128 nodes x 64 j ----
    for (int idx = tid; idx < 128 * 64; idx += 256) {
        int m = idx >> 6, j = idx & 63;
        int n = n0 + m;
        float v = (n < N_NODES) ? h[(size_t)n * 64 + j] : 0.0f;
        __half hv = __float2half_rn(v);
        int mt = m >> 4, mm = m & 15;
        int ks = j >> 4, kk = j & 15;
        int flane = (mm & 7) * 4 + ((kk & 7) >> 1);
        int reg = (mm >> 3) | ((kk >> 3) << 1);
        int half_sel = kk & 1;
        uint32_t off = (uint32_t)(((mt * 4 + ks) * 32 + flane) * 16 + reg * 4 +
                                  half_sel * 2);
        *(__half*)(smdyn + OFF_AH + off) = hv;
    }
    __syncthreads();

    // preload all A fragments for this warp's m-tile into registers
    uint4 aR[4];
#pragma unroll
    for (int ks = 0; ks < 4; ks++)
        aR[ks] = *(const uint4*)(smdyn + OFF_AH + ((w * 4 + ks) * 32 + lane) * 16);

    float acc[16][4];
#pragma unroll
    for (int nt = 0; nt < 16; nt++)
#pragma unroll
        for (int r = 0; r < 4; r++) acc[nt][r] = 0.0f;

#pragma unroll
    for (int ks = 0; ks < 4; ks++) {
#pragma unroll
        for (int nt = 0; nt < 16; nt++) {
            uint2 b = *(const uint2*)(smdyn + OFF_BF + ((nt * 4 + ks) * 32 + lane) * 8);
            mma_f16_k16(acc[nt], aR[ks].x, aR[ks].y, aR[ks].z, aR[ks].w, b.x, b.y);
        }
    }

    // ---- epilogue: fp16 convert, smem restage (pitch 272B), STG.128 ----
    __syncthreads();                       // all warps done reading fragments
    uint32_t wbase = (uint32_t)w * 4352;   // 16 rows * 272 B per warp
    int r = lane >> 2, cq = lane & 3;
#pragma unroll
    for (int nt = 0; nt < 16; nt++) {
        *(__half2*)(smdyn + wbase + r * 272 + nt * 16 + cq * 4) =
            __floats2half2_rn(acc[nt][0], acc[nt][1]);
        *(__half2*)(smdyn + wbase + (r + 8) * 272 + nt * 16 + cq * 4) =
            __floats2half2_rn(acc[nt][2], acc[nt][3]);
    }
    __syncwarp();
    int rr = lane >> 3, seg = lane & 7;
#pragma unroll
    for (int it = 0; it < 4; it++) {
#pragma unroll
        for (int j = 0; j < 2; j++) {
            int r2 = rr + it * 4;
            uint4 vv = *(const uint4*)(smdyn + wbase + r2 * 272 + (seg * 2 + j) * 16);
            int gr = rowloc0 + w * 16 + r2;       // local row in pass buffer
            size_t col = c0 + (size_t)(seg * 2 + j) * 8;
            __stcs((uint4*)(g_M + (size_t)gr * NCOLS + col), vv);
        }
    }
}

// ---------------- Stage 2: m[e,i] = sum_k hid[e,k]*M[n,k*64+i] + cb[i] ----------------
// BLOCKED edge mapping: warp s handles edges 3s..3s+2 (dense), so a degree-6
// node activates 2 warps with 3 accumulators each instead of 6 warps with 1 —
// Ms crossbar traffic /3. Ms kept RAW fp16 in smem (straight uint4 copy, no
// fill conversion; one half2->float2 cvt per k per warp, amortized over up
// to 6 FMAs) — Ms bytes /2 again.
#define S2_BODY(NACC)                                                         \
    _Pragma("unroll 4")                                                       \
    for (int k = 0; k < 128; k++) {                                           \
        float2 mm = __half22float2(((const __half2*)Ms)[k * 32 + il]);        \
        float h0 = hidS[e0s * 128 + k];                                       \
        a0.x = fmaf(h0, mm.x, a0.x);                                          \
        a0.y = fmaf(h0, mm.y, a0.y);                                          \
        if (NACC > 1) {                                                       \
            float h1 = hidS[(e0s + 1) * 128 + k];                             \
            a1.x = fmaf(h1, mm.x, a1.x);                                      \
            a1.y = fmaf(h1, mm.y, a1.y);                                      \
        }                                                                     \
        if (NACC > 2) {                                                       \
            float h2v = hidS[(e0s + 2) * 128 + k];                            \
            a2.x = fmaf(h2v, mm.x, a2.x);                                     \
            a2.y = fmaf(h2v, mm.y, a2.y);                                     \
        }                                                                     \
    }

__global__ void __launch_bounds__(256) k_stage2(const float* __restrict__ h,
                                                const float* __restrict__ b2,
                                                float* __restrict__ out,
                                                int n_base) {
    __shared__ __align__(16) __half Ms[128 * 64];     // 16 KB raw fp16 [k][i]
    __shared__ __align__(16) float hidS[24 * 128];    // 12 KB [slot24][k128]
    __shared__ float hS[64];
    __shared__ float cb[64];
    __shared__ int eS[24];

    int n = n_base + blockIdx.x;
    if (n >= N_NODES) return;
    int start = g_off[n], end = g_off[n + 1];
    if (start == end) return;

    int tid = threadIdx.x;
    int s = tid >> 5;
    int il = tid & 31;
    int i2 = il * 2;
    int e0s = 3 * s;          // first local edge owned by this warp

    if (tid < 64) hS[tid] = h[(size_t)n * 64 + tid];
    __syncthreads();
    if (s == 0) {
        float c0 = 0.f, c1 = 0.f;
#pragma unroll 8
        for (int j = 0; j < 64; j++) {
            float hv = hS[j];
            c0 = fmaf(b2[i2 * 64 + j], hv, c0);
            c1 = fmaf(b2[(i2 + 1) * 64 + j], hv, c1);
        }
        cb[i2] = c0; cb[i2 + 1] = c1;
    }

    const __half* Mrow = g_M + (size_t)(n - n_base) * NCOLS;

    for (int base = start; base < end; base += 24) {
        int cnt = min(24, end - base);
        __syncthreads();
        if (tid < cnt) eS[tid] = g_perm[base + tid];
        __syncthreads();

        float2 a0 = make_float2(cb[i2], cb[i2 + 1]);
        float2 a1 = a0, a2 = a0;
        int nacc = min(3, cnt - e0s);   // may be <=0 for idle warps

        for (int kc = 0; kc < 32; kc++) {
            __syncthreads();
            // raw fp16 copy of the M chunk (16 KB): layout preserved
            const uint4* msrc = (const uint4*)(Mrow + (size_t)kc * 8192);
            for (int u = tid; u < 1024; u += 256)
                ((uint4*)Ms)[u] = __ldcs(msrc + u);
            // hid chunk -> fp32 (reads are broadcast; convert once at fill)
            for (int u = tid; u < cnt * 32; u += 256) {
                int v = u >> 5, q = u & 31;
                const uint2* hsrc =
                    (const uint2*)(g_hid + (size_t)eS[v] * H2 + kc * 128);
                uint2 raw = __ldcs(hsrc + q);
                __half2* hp = (__half2*)&raw;
                float2 f0 = __half22float2(hp[0]);
                float2 f1 = __half22float2(hp[1]);
                ((float4*)(hidS + v * 128))[q] = make_float4(f0.x, f0.y, f1.x, f1.y);
            }
            __syncthreads();
            switch (nacc) {
                case 1: { S2_BODY(1) } break;
                case 2: { S2_BODY(2) } break;
                case 3: { S2_BODY(3) } break;
                default: break;
            }
        }
        if (nacc > 0) *(float2*)&out[(size_t)eS[e0s] * 64 + i2] = a0;
        if (nacc > 1) *(float2*)&out[(size_t)eS[e0s + 1] * 64 + i2] = a1;
        if (nacc > 2) *(float2*)&out[(size_t)eS[e0s + 2] * 64 + i2] = a2;
    }
}

// ---------------- dst passthrough ----------------
__global__ void k_dst(const int* __restrict__ ei, float* __restrict__ out) {
    int e = blockIdx.x * blockDim.x + threadIdx.x;
    if (e < N_EDGES) out[(size_t)N_EDGES * 64 + e] = (float)ei[N_EDGES + e];
}

// ---------------- launch ----------------
extern "C" void kernel_launch(void* const* d_in, const int* in_sizes, int n_in,
                              void* d_out, int out_size) {
    const float* h  = (const float*)d_in[0];
    const int*   ei = (const int*)d_in[1];
    const float* ea = (const float*)d_in[2];
    const float* W1 = (const float*)d_in[3];
    const float* b1 = (const float*)d_in[4];
    const float* W2 = (const float*)d_in[5];
    const float* b2 = (const float*)d_in[6];
    float* out = (float*)d_out;

    k_csr<<<1, 1024>>>(ei);
    k_hid<<<N_EDGES / HID_EB, 256>>>(ea, W1, b1);

    cudaFuncSetAttribute(k_gemm1, cudaFuncAttributeMaxDynamicSharedMemorySize,
                         G1_SMEM);

    for (int p = 0; p < N_PASSES; p++) {
        int n_base = p * PASS_NODES;
        int rem = N_NODES - n_base;
        int nodes = rem < PASS_NODES ? rem : PASS_NODES;
        dim3 g1(2048, (nodes + 127) / 128);    // col-blocks x row-groups
        k_gemm1<<<g1, 256, G1_SMEM>>>(h, W2, n_base);
        k_stage2<<<nodes, 256>>>(h, b2, out, n_base);
    }

    if (out_size > N_EDGES * 64)
        k_dst<<<(N_EDGES + 255) / 256, 256>>>(ei, out);
}